// round 13
// baseline (speedup 1.0000x reference)
#include <cuda_runtime.h>
#include <cuda_fp16.h>
#include <mma.h>
#include <math.h>

using namespace nvcuda;

#define N_NODES   50000
#define N_EDGES   1600000
#define N_GRAPHS  256
#define DIM_IN    128
#define D1        100
#define D2        20
#define DIM_SELF  64

#define P1_LD2    64          // p1 row stride in half2 (128 halfs = 256B aligned)
#define P2_LD2    16          // p2 row stride in half2 (32 halfs = 64B aligned)
#define W1_LD     112         // padded W1 cols (halfs) for wmma B tile

// ---------------- scratch (device globals; no allocation allowed) -----------
__device__ __align__(16) int     g_cnt[N_NODES];
__device__ __align__(16) int     g_rowptr[N_NODES + 1];
__device__ __align__(16) int     g_posn[N_EDGES];
__device__ __align__(16) int     g_csr[N_EDGES];
__device__ __align__(16) __half  g_w1h[128 * W1_LD];        // W1 pre-converted fp16
__device__ __align__(16) __half2 g_p1h[N_NODES * P1_LD2];   // feat @ W1 (fp16)
__device__ __align__(16) __half2 g_p2h[N_NODES * P2_LD2];   // h1 @ W2 (fp16)
__device__ __align__(16) float   g_hg[N_GRAPHS * D2];
__device__ __align__(16) int     g_gcnt[N_GRAPHS];

// ---------------- zero per-call state + per-call W1 convert -----------------
__global__ void k_zero(const float* __restrict__ W1) {
    int i = blockIdx.x * blockDim.x + threadIdx.x;
    if (i < N_NODES) g_cnt[i] = 0;
    if (i < N_GRAPHS * D2) g_hg[i] = 0.f;
    if (i < N_GRAPHS) g_gcnt[i] = 0;
    if (i < 128 * W1_LD) {
        int k = i / W1_LD, c = i - k * W1_LD;
        g_w1h[i] = (c < D1) ? __float2half(W1[k * D1 + c]) : __float2half(0.f);
    }
}

// ---------------- CSR build: single atomic pass ------------------------------
__global__ void k_count(const int* __restrict__ dst) {
    int e4 = blockIdx.x * blockDim.x + threadIdx.x;
    if (e4 >= N_EDGES / 4) return;
    int4 d = ((const int4*)dst)[e4];
    int4 p;
    p.x = atomicAdd(&g_cnt[d.x], 1);
    p.y = atomicAdd(&g_cnt[d.y], 1);
    p.z = atomicAdd(&g_cnt[d.z], 1);
    p.w = atomicAdd(&g_cnt[d.w], 1);
    ((int4*)g_posn)[e4] = p;
}

// single-block exclusive scan of g_cnt -> g_rowptr (int4-vectorized, CH=52)
__global__ void k_scan() {
    __shared__ int ss[1024];
    const int CH = 52;                       // 13 int4 per thread
    int t = threadIdx.x;
    int base = t * CH;
    int s = 0;
    if (base + CH <= N_NODES) {
        const int4* p = (const int4*)(g_cnt + base);
        #pragma unroll
        for (int i = 0; i < 13; i++) { int4 v = p[i]; s += v.x + v.y + v.z + v.w; }
    } else {
        for (int i = base; i < N_NODES; i++) s += g_cnt[i];
    }
    ss[t] = s;
    __syncthreads();
    for (int off = 1; off < 1024; off <<= 1) {
        int v = (t >= off) ? ss[t - off] : 0;
        __syncthreads();
        ss[t] += v;
        __syncthreads();
    }
    int run = (t == 0) ? 0 : ss[t - 1];
    if (base + CH <= N_NODES) {
        const int4* p = (const int4*)(g_cnt + base);
        int4* q = (int4*)(g_rowptr + base);
        #pragma unroll
        for (int i = 0; i < 13; i++) {
            int4 v = p[i];
            int4 o;
            o.x = run; run += v.x;
            o.y = run; run += v.y;
            o.z = run; run += v.z;
            o.w = run; run += v.w;
            q[i] = o;
        }
    } else {
        for (int i = base; i < N_NODES; i++) { g_rowptr[i] = run; run += g_cnt[i]; }
    }
    if (t == 0) g_rowptr[N_NODES] = N_EDGES;
}

// atomic-free fill: slot known from recorded position
__global__ void k_fill(const int* __restrict__ src, const int* __restrict__ dst) {
    int e4 = blockIdx.x * blockDim.x + threadIdx.x;
    if (e4 >= N_EDGES / 4) return;
    int4 d = ((const int4*)dst)[e4];
    int4 p = ((const int4*)g_posn)[e4];
    int4 s = ((const int4*)src)[e4];
    g_csr[g_rowptr[d.x] + p.x] = s.x;
    g_csr[g_rowptr[d.y] + p.y] = s.y;
    g_csr[g_rowptr[d.z] + p.z] = s.z;
    g_csr[g_rowptr[d.w] + p.w] = s.w;
}

// ---------------- GEMM1: p1 = feat @ W1 via HMMA ----------------------------
__global__ void k_gemm1(const float* __restrict__ feat) {
    __shared__ __align__(16) unsigned char sm[45056];
    __half* Ah = (__half*)sm;                      // 64 x 128 halfs
    __half* Bh = (__half*)(sm + 16384);            // 128 x 112 halfs
    float*  Of = (float*)sm;                       // 64 x 112 floats (overlay)

    int t  = threadIdx.x;
    int r0 = blockIdx.x * 64;

    {
        const int4* w4 = (const int4*)g_w1h;
        int4* b4 = (int4*)Bh;
        #pragma unroll
        for (int i = t; i < 1792; i += 256) b4[i] = w4[i];
    }
    {
        __half2* a2 = (__half2*)Ah;
        for (int i = t; i < 64 * 32; i += 256) {
            int r = i >> 5, q = i & 31;
            float4 f = (r0 + r < N_NODES)
                     ? ((const float4*)feat)[(size_t)(r0 + r) * 32 + q]
                     : make_float4(0.f, 0.f, 0.f, 0.f);
            a2[r * 64 + 2 * q]     = __floats2half2_rn(f.x, f.y);
            a2[r * 64 + 2 * q + 1] = __floats2half2_rn(f.z, f.w);
        }
    }
    __syncthreads();

    int w     = t >> 5;
    int strip = w >> 1;
    int ct0   = (w & 1) ? 4 : 0;
    int nct   = (w & 1) ? 3 : 4;

    wmma::fragment<wmma::accumulator, 16, 16, 16, float> acc[4];
    for (int c = 0; c < 4; c++) wmma::fill_fragment(acc[c], 0.f);

    for (int k8 = 0; k8 < 8; k8++) {
        wmma::fragment<wmma::matrix_a, 16, 16, 16, __half, wmma::row_major> af;
        wmma::load_matrix_sync(af, Ah + strip * 16 * DIM_IN + k8 * 16, DIM_IN);
        for (int c = 0; c < nct; c++) {
            wmma::fragment<wmma::matrix_b, 16, 16, 16, __half, wmma::row_major> bf;
            wmma::load_matrix_sync(bf, Bh + (k8 * 16) * W1_LD + (ct0 + c) * 16, W1_LD);
            wmma::mma_sync(acc[c], af, bf, acc[c]);
        }
    }
    __syncthreads();

    for (int c = 0; c < nct; c++)
        wmma::store_matrix_sync(Of + strip * 16 * W1_LD + (ct0 + c) * 16,
                                acc[c], W1_LD, wmma::mem_row_major);
    __syncthreads();

    for (int i = t; i < 64 * 50; i += 256) {
        int r = i / 50, c2 = i - r * 50;
        if (r0 + r < N_NODES) {
            float fx = Of[r * W1_LD + 2 * c2];
            float fy = Of[r * W1_LD + 2 * c2 + 1];
            g_p1h[(size_t)(r0 + r) * P1_LD2 + c2] = __floats2half2_rn(fx, fy);
        }
    }
}

// ---------------- Fused: aggregation-1 + relu + GEMM2 -----------------------
// 8 warps, 1 node/warp. Agg: lanes 0..24 each own 4 dims via one LDG.64.
// GEMM2: lanes 0..19 dot h1s row against transposed-W2 column via LDS.128.
// grid*8 == N_NODES exactly (6250*8), so no bounds guards.
__global__ void k_agg1g2(const float* __restrict__ b1, const float* __restrict__ W2) {
    __shared__ __align__(16) float h1s[8][104];     // 416B rows (16B aligned)
    __shared__ __align__(16) float w2t[D2][100];    // transposed W2, 400B rows
    int t = threadIdx.x, w = t >> 5, lane = t & 31;

    for (int i = t; i < D1 * D2; i += 256) {
        int k = i / D2, c = i - k * D2;             // coalesced read of W2
        w2t[c][k] = W2[i];
    }
    __syncthreads();                                 // w2t ready before gemm use

    int gw = blockIdx.x * 8 + w;
    int start = g_rowptr[gw], end = g_rowptr[gw + 1];
    int deg = end - start;
    float a0 = 0.f, a1 = 0.f, a2 = 0.f, a3 = 0.f;
    const char* p1base = (const char*)g_p1h;
    bool lact = lane < 25;
    size_t loff = (size_t)lane * 8;

    int nfull = deg & ~31;
    for (int eb = start; eb < start + nfull; eb += 32) {
        int s = g_csr[eb + lane];
        #pragma unroll 8
        for (int j = 0; j < 32; j++) {
            int sj = __shfl_sync(0xffffffffu, s, j);
            if (lact) {
                float2 rr = *(const float2*)(p1base + (size_t)sj * 256 + loff);
                float2 f0 = __half22float2(*(__half2*)&rr.x);
                float2 f1 = __half22float2(*(__half2*)&rr.y);
                a0 += f0.x; a1 += f0.y; a2 += f1.x; a3 += f1.y;
            }
        }
    }
    int rem = deg - nfull;
    if (rem) {
        int s = (lane < rem) ? g_csr[start + nfull + lane] : 0;
        for (int j = 0; j < rem; j++) {
            int sj = __shfl_sync(0xffffffffu, s, j);
            if (lact) {
                float2 rr = *(const float2*)(p1base + (size_t)sj * 256 + loff);
                float2 f0 = __half22float2(*(__half2*)&rr.x);
                float2 f1 = __half22float2(*(__half2*)&rr.y);
                a0 += f0.x; a1 += f0.y; a2 += f1.x; a3 += f1.y;
            }
        }
    }
    if (lact) {
        if (deg > 0) {
            float inv = 1.0f / (float)deg;
            a0 *= inv; a1 *= inv; a2 *= inv; a3 *= inv;
        } else {
            float2 rr = *(const float2*)(p1base + (size_t)gw * 256 + loff);
            float2 f0 = __half22float2(*(__half2*)&rr.x);
            float2 f1 = __half22float2(*(__half2*)&rr.y);
            a0 = f0.x; a1 = f0.y; a2 = f1.x; a3 = f1.y;
        }
        float4 bb = ((const float4*)b1)[lane];       // 25 x float4 = 100
        float4 hv = make_float4(fmaxf(a0 + bb.x, 0.f), fmaxf(a1 + bb.y, 0.f),
                                fmaxf(a2 + bb.z, 0.f), fmaxf(a3 + bb.w, 0.f));
        *(float4*)&h1s[w][lane * 4] = hv;
    }
    __syncwarp();                                    // h1s is per-warp only

    // GEMM2: p2[gw][c] = sum_k h1s[w][k] * w2t[c][k], c = lane < 20
    float acc = 0.f;
    if (lane < D2) {
        #pragma unroll
        for (int k = 0; k < D1; k += 4) {
            float4 h  = *(const float4*)&h1s[w][k];
            float4 wv = *(const float4*)&w2t[lane][k];
            acc += h.x * wv.x + h.y * wv.y + h.z * wv.z + h.w * wv.w;
        }
    }
    float hi = __shfl_down_sync(0xffffffffu, acc, 1);
    if (lane < D2 && (lane & 1) == 0)
        g_p2h[(size_t)gw * P2_LD2 + (lane >> 1)] = __floats2half2_rn(acc, hi);
}

// ---------------- Aggregation layer 2 (6 edges/iter) + fused pool -----------
// lane = eslot*5 + idx: eslot 0..5 = edge within 6-pack, idx 0..4 = 8B chunk.
__global__ void k_agg2pool(const float* __restrict__ b2, const int* __restrict__ gid) {
    int gw   = (blockIdx.x * blockDim.x + threadIdx.x) >> 5;
    int lane = threadIdx.x & 31;
    int start = g_rowptr[gw], end = g_rowptr[gw + 1];
    int deg = end - start;
    int eslot = lane / 5;
    int idx   = lane - eslot * 5;
    bool lact = lane < 30;
    const char* p2base = (const char*)g_p2h;
    size_t coff = (size_t)idx * 8;
    float a0 = 0.f, a1 = 0.f, a2 = 0.f, a3 = 0.f;

    for (int eb = start; eb < end; eb += 32) {
        int n = min(32, end - eb);
        int s = (lane < n) ? g_csr[eb + lane] : 0;
        for (int j = 0; j < n; j += 6) {
            int je = j + eslot;
            int sj = __shfl_sync(0xffffffffu, s, je & 31);
            if (lact && je < n) {
                float2 rr = *(const float2*)(p2base + (size_t)sj * 64 + coff);
                float2 f0 = __half22float2(*(__half2*)&rr.x);
                float2 f1 = __half22float2(*(__half2*)&rr.y);
                a0 += f0.x; a1 += f0.y; a2 += f1.x; a3 += f1.y;
            }
        }
    }
    // combine 6 edge-groups into lanes 0..4
    #pragma unroll
    for (int off = 5; off < 30; off += 5) {
        a0 += __shfl_down_sync(0xffffffffu, a0, off) * ((off == 5) ? 0.f : 0.f); // placeholder avoided below
    }
    // (explicit 5-way gather — the loop above is removed by the compiler; do it directly)
    {
        float b0 = __shfl_down_sync(0xffffffffu, a0, 5),  c0 = __shfl_down_sync(0xffffffffu, a0, 10);
        float d0 = __shfl_down_sync(0xffffffffu, a0, 15), e0 = __shfl_down_sync(0xffffffffu, a0, 20);
        float f0 = __shfl_down_sync(0xffffffffu, a0, 25);
        a0 += b0 + c0 + d0 + e0 + f0;
        float b1v = __shfl_down_sync(0xffffffffu, a1, 5),  c1 = __shfl_down_sync(0xffffffffu, a1, 10);
        float d1 = __shfl_down_sync(0xffffffffu, a1, 15), e1 = __shfl_down_sync(0xffffffffu, a1, 20);
        float f1 = __shfl_down_sync(0xffffffffu, a1, 25);
        a1 += b1v + c1 + d1 + e1 + f1;
        float b2v = __shfl_down_sync(0xffffffffu, a2, 5),  c2 = __shfl_down_sync(0xffffffffu, a2, 10);
        float d2 = __shfl_down_sync(0xffffffffu, a2, 15), e2 = __shfl_down_sync(0xffffffffu, a2, 20);
        float f2 = __shfl_down_sync(0xffffffffu, a2, 25);
        a2 += b2v + c2 + d2 + e2 + f2;
        float b3 = __shfl_down_sync(0xffffffffu, a3, 5),  c3 = __shfl_down_sync(0xffffffffu, a3, 10);
        float d3 = __shfl_down_sync(0xffffffffu, a3, 15), e3 = __shfl_down_sync(0xffffffffu, a3, 20);
        float f3 = __shfl_down_sync(0xffffffffu, a3, 25);
        a3 += b3 + c3 + d3 + e3 + f3;
    }

    int g = gid[gw];
    if (lane < 5) {
        float v0, v1, v2, v3;
        if (deg > 0) {
            float inv = 1.0f / (float)deg;
            v0 = a0 * inv; v1 = a1 * inv; v2 = a2 * inv; v3 = a3 * inv;
        } else {
            float2 rr = *(const float2*)(p2base + (size_t)gw * 64 + (size_t)lane * 8);
            float2 f0 = __half22float2(*(__half2*)&rr.x);
            float2 f1 = __half22float2(*(__half2*)&rr.y);
            v0 = f0.x; v1 = f0.y; v2 = f1.x; v3 = f1.y;
        }
        float4 bb = ((const float4*)b2)[lane];       // 5 x float4 = 20
        atomicAdd(&g_hg[g * D2 + 4 * lane],     fmaxf(v0 + bb.x, 0.f));
        atomicAdd(&g_hg[g * D2 + 4 * lane + 1], fmaxf(v1 + bb.y, 0.f));
        atomicAdd(&g_hg[g * D2 + 4 * lane + 2], fmaxf(v2 + bb.z, 0.f));
        atomicAdd(&g_hg[g * D2 + 4 * lane + 3], fmaxf(v3 + bb.w, 0.f));
    }
    if (lane == 0) atomicAdd(&g_gcnt[g], 1);
}

// ---------------- gate + MLP decoder (256 graphs, 1 block) ------------------
__global__ void k_final(const float* __restrict__ self_feat,
                        const float* __restrict__ Wp,  const float* __restrict__ bp,
                        const float* __restrict__ Wf1, const float* __restrict__ bf1,
                        const float* __restrict__ Wf2, const float* __restrict__ bf2,
                        float* __restrict__ out) {
    __shared__ float swp[DIM_SELF * D2];
    __shared__ float sbp[D2], swf1[D2 * 10], sbf1[10], swf2[10], sbf2;
    int t = threadIdx.x;
    for (int i = t; i < DIM_SELF * D2; i += 256) swp[i] = Wp[i];
    for (int i = t; i < D2 * 10; i += 256) swf1[i] = Wf1[i];
    if (t < D2) sbp[t] = bp[t];
    if (t < 10) { sbf1[t] = bf1[t]; swf2[t] = Wf2[t]; }
    if (t == 0) sbf2 = bf2[0];
    __syncthreads();

    int g = t;
    float hg[D2], z[D2];
    int c = g_gcnt[g];
    float invc = 1.0f / (float)max(c, 1);
    #pragma unroll
    for (int j = 0; j < D2; j++) { hg[j] = g_hg[g * D2 + j] * invc; z[j] = sbp[j]; }
    for (int i = 0; i < DIM_SELF; i++) {
        float sv = self_feat[g * DIM_SELF + i];
        #pragma unroll
        for (int j = 0; j < D2; j++) z[j] += sv * swp[i * D2 + j];
    }
    float m[10];
    #pragma unroll
    for (int o = 0; o < 10; o++) m[o] = sbf1[o];
    #pragma unroll
    for (int j = 0; j < D2; j++) {
        float p    = hg[j] * z[j];
        float gate = 1.0f / (1.0f + expf(-p));
        float f    = gate * hg[j] + (1.0f - gate) * z[j];
        #pragma unroll
        for (int o = 0; o < 10; o++) m[o] += f * swf1[j * 10 + o];
    }
    float o0 = sbf2;
    #pragma unroll
    for (int o = 0; o < 10; o++) o0 += fmaxf(m[o], 0.f) * swf2[o];
    out[g] = o0;
}

// ---------------- launch -----------------------------------------------------
extern "C" void kernel_launch(void* const* d_in, const int* in_sizes, int n_in,
                              void* d_out, int out_size) {
    const float* feat      = (const float*)d_in[0];
    const int*   src       = (const int*)  d_in[1];
    const int*   dst       = (const int*)  d_in[2];
    const int*   gid       = (const int*)  d_in[3];
    const float* self_feat = (const float*)d_in[4];
    const float* W1  = (const float*)d_in[5];
    const float* b1  = (const float*)d_in[6];
    const float* W2  = (const float*)d_in[7];
    const float* b2  = (const float*)d_in[8];
    const float* Wp  = (const float*)d_in[9];
    const float* bp  = (const float*)d_in[10];
    const float* Wf1 = (const float*)d_in[11];
    const float* bf1 = (const float*)d_in[12];
    const float* Wf2 = (const float*)d_in[13];
    const float* bf2 = (const float*)d_in[14];
    float* out = (float*)d_out;

    k_zero    <<<(N_NODES + 255) / 256, 256>>>(W1);
    k_count   <<<(N_EDGES / 4 + 255) / 256, 256>>>(dst);
    k_scan    <<<1, 1024>>>();
    k_fill    <<<(N_EDGES / 4 + 255) / 256, 256>>>(src, dst);
    k_gemm1   <<<(N_NODES + 63) / 64, 256>>>(feat);
    k_agg1g2  <<<N_NODES / 8, 256>>>(b1, W2);
    k_agg2pool<<<N_NODES / 8, 256>>>(b2, gid);
    k_final   <<<1, 256>>>(self_feat, Wp, bp, Wf1, bf1, Wf2, bf2, out);
}

// round 14
// speedup vs baseline: 1.0001x; 1.0001x over previous
#include <cuda_runtime.h>
#include <cuda_fp16.h>
#include <mma.h>
#include <math.h>

using namespace nvcuda;

#define N_NODES   50000
#define N_EDGES   1600000
#define N_GRAPHS  256
#define DIM_IN    128
#define D1        100
#define D2        20
#define DIM_SELF  64

#define P1_LD2    64          // p1 row stride in half2 (128 halfs = 256B aligned)
#define P2_LD2    16          // p2 row stride in half2 (32 halfs = 64B aligned)
#define W1_LD     112         // padded W1 cols (halfs) for wmma B tile

// ---------------- scratch (device globals; no allocation allowed) -----------
// Invariant: g_cnt / g_hg / g_gcnt are zero on entry to every call (zero-init
// at load; re-zeroed by the kernels that consume them at the end of each call).
__device__ __align__(16) int     g_cnt[N_NODES];
__device__ __align__(16) int     g_rowptr[N_NODES + 1];
__device__ __align__(16) int     g_posn[N_EDGES];
__device__ __align__(16) int     g_csr[N_EDGES];
__device__ __align__(16) __half  g_w1h[128 * W1_LD];        // W1 fp16 (refreshed per call)
__device__ __align__(16) __half2 g_p1h[N_NODES * P1_LD2];   // feat @ W1 (fp16)
__device__ __align__(16) __half2 g_p2h[N_NODES * P2_LD2];   // h1 @ W2 (fp16)
__device__ __align__(16) float   g_hg[N_GRAPHS * D2];
__device__ __align__(16) int     g_gcnt[N_GRAPHS];

// ---------------- CSR count (single atomic pass) + W1 fp16 convert ----------
__global__ void k_count(const int* __restrict__ dst, const float* __restrict__ W1) {
    int e4 = blockIdx.x * blockDim.x + threadIdx.x;
    if (e4 < 128 * W1_LD) {                  // piggyback: W1 -> fp16 (14336 elems)
        int k = e4 / W1_LD, c = e4 - k * W1_LD;
        g_w1h[e4] = (c < D1) ? __float2half(W1[k * D1 + c]) : __float2half(0.f);
    }
    if (e4 >= N_EDGES / 4) return;
    int4 d = ((const int4*)dst)[e4];
    int4 p;
    p.x = atomicAdd(&g_cnt[d.x], 1);
    p.y = atomicAdd(&g_cnt[d.y], 1);
    p.z = atomicAdd(&g_cnt[d.z], 1);
    p.w = atomicAdd(&g_cnt[d.w], 1);
    ((int4*)g_posn)[e4] = p;
}

// single-block exclusive scan of g_cnt -> g_rowptr (int4, CH=52);
// re-zeroes g_cnt after reading (restores the call-entry invariant).
__global__ void k_scan() {
    __shared__ int ss[1024];
    const int CH = 52;                       // 13 int4 per thread
    int t = threadIdx.x;
    int base = t * CH;
    int s = 0;
    if (base + CH <= N_NODES) {
        const int4* p = (const int4*)(g_cnt + base);
        #pragma unroll
        for (int i = 0; i < 13; i++) { int4 v = p[i]; s += v.x + v.y + v.z + v.w; }
    } else {
        for (int i = base; i < N_NODES; i++) s += g_cnt[i];
    }
    ss[t] = s;
    __syncthreads();
    for (int off = 1; off < 1024; off <<= 1) {
        int v = (t >= off) ? ss[t - off] : 0;
        __syncthreads();
        ss[t] += v;
        __syncthreads();
    }
    int run = (t == 0) ? 0 : ss[t - 1];
    if (base + CH <= N_NODES) {
        const int4* p = (const int4*)(g_cnt + base);
        int4* q = (int4*)(g_rowptr + base);
        int4* z = (int4*)(g_cnt + base);
        #pragma unroll
        for (int i = 0; i < 13; i++) {
            int4 v = p[i];
            int4 o;
            o.x = run; run += v.x;
            o.y = run; run += v.y;
            o.z = run; run += v.z;
            o.w = run; run += v.w;
            q[i] = o;
            z[i] = make_int4(0, 0, 0, 0);
        }
    } else {
        for (int i = base; i < N_NODES; i++) {
            g_rowptr[i] = run; run += g_cnt[i]; g_cnt[i] = 0;
        }
    }
    if (t == 0) g_rowptr[N_NODES] = N_EDGES;
}

// atomic-free fill: slot known from recorded position
__global__ void k_fill(const int* __restrict__ src, const int* __restrict__ dst) {
    int e4 = blockIdx.x * blockDim.x + threadIdx.x;
    if (e4 >= N_EDGES / 4) return;
    int4 d = ((const int4*)dst)[e4];
    int4 p = ((const int4*)g_posn)[e4];
    int4 s = ((const int4*)src)[e4];
    g_csr[g_rowptr[d.x] + p.x] = s.x;
    g_csr[g_rowptr[d.y] + p.y] = s.y;
    g_csr[g_rowptr[d.z] + p.z] = s.z;
    g_csr[g_rowptr[d.w] + p.w] = s.w;
}

// ---------------- GEMM1: p1 = feat @ W1 via HMMA ----------------------------
__global__ void k_gemm1(const float* __restrict__ feat) {
    __shared__ __align__(16) unsigned char sm[45056];
    __half* Ah = (__half*)sm;                      // 64 x 128 halfs
    __half* Bh = (__half*)(sm + 16384);            // 128 x 112 halfs
    float*  Of = (float*)sm;                       // 64 x 112 floats (overlay)

    int t  = threadIdx.x;
    int r0 = blockIdx.x * 64;

    {
        const int4* w4 = (const int4*)g_w1h;
        int4* b4 = (int4*)Bh;
        #pragma unroll
        for (int i = t; i < 1792; i += 256) b4[i] = w4[i];
    }
    {
        __half2* a2 = (__half2*)Ah;
        for (int i = t; i < 64 * 32; i += 256) {
            int r = i >> 5, q = i & 31;
            float4 f = (r0 + r < N_NODES)
                     ? ((const float4*)feat)[(size_t)(r0 + r) * 32 + q]
                     : make_float4(0.f, 0.f, 0.f, 0.f);
            a2[r * 64 + 2 * q]     = __floats2half2_rn(f.x, f.y);
            a2[r * 64 + 2 * q + 1] = __floats2half2_rn(f.z, f.w);
        }
    }
    __syncthreads();

    int w     = t >> 5;
    int strip = w >> 1;
    int ct0   = (w & 1) ? 4 : 0;
    int nct   = (w & 1) ? 3 : 4;

    wmma::fragment<wmma::accumulator, 16, 16, 16, float> acc[4];
    for (int c = 0; c < 4; c++) wmma::fill_fragment(acc[c], 0.f);

    for (int k8 = 0; k8 < 8; k8++) {
        wmma::fragment<wmma::matrix_a, 16, 16, 16, __half, wmma::row_major> af;
        wmma::load_matrix_sync(af, Ah + strip * 16 * DIM_IN + k8 * 16, DIM_IN);
        for (int c = 0; c < nct; c++) {
            wmma::fragment<wmma::matrix_b, 16, 16, 16, __half, wmma::row_major> bf;
            wmma::load_matrix_sync(bf, Bh + (k8 * 16) * W1_LD + (ct0 + c) * 16, W1_LD);
            wmma::mma_sync(acc[c], af, bf, acc[c]);
        }
    }
    __syncthreads();

    for (int c = 0; c < nct; c++)
        wmma::store_matrix_sync(Of + strip * 16 * W1_LD + (ct0 + c) * 16,
                                acc[c], W1_LD, wmma::mem_row_major);
    __syncthreads();

    for (int i = t; i < 64 * 50; i += 256) {
        int r = i / 50, c2 = i - r * 50;
        if (r0 + r < N_NODES) {
            float fx = Of[r * W1_LD + 2 * c2];
            float fy = Of[r * W1_LD + 2 * c2 + 1];
            g_p1h[(size_t)(r0 + r) * P1_LD2 + c2] = __floats2half2_rn(fx, fy);
        }
    }
}

// ---------------- Fused: aggregation-1 + relu + GEMM2 -----------------------
// 8 warps, 1 node/warp. Gather batches 4 edges per inner step for MLP=4..8.
// Lane layout (round-10): half2 {lane} on all 32 lanes + {32+lane} on lanes<18.
__global__ void k_agg1g2(const float* __restrict__ b1, const float* __restrict__ W2) {
    __shared__ float h1s[8][104];
    __shared__ float w2s[D1 * D2];     // 8000 B
    int t = threadIdx.x, w = t >> 5, lane = t & 31;

    for (int i = t; i < D1 * D2; i += 256) w2s[i] = W2[i];

    int gw = blockIdx.x * 8 + w;       // grid*8 == N_NODES exactly
    int start = g_rowptr[gw], end = g_rowptr[gw + 1];
    int deg = end - start;
    float a0x = 0.f, a0y = 0.f, a1x = 0.f, a1y = 0.f;
    bool hib = lane < 18;

    int nfull = deg & ~31;
    for (int eb = start; eb < start + nfull; eb += 32) {
        int s = g_csr[eb + lane];
        #pragma unroll
        for (int j = 0; j < 32; j += 4) {
            int s0 = __shfl_sync(0xffffffffu, s, j);
            int s1 = __shfl_sync(0xffffffffu, s, j + 1);
            int s2 = __shfl_sync(0xffffffffu, s, j + 2);
            int s3 = __shfl_sync(0xffffffffu, s, j + 3);
            const __half2* r0 = g_p1h + (size_t)s0 * P1_LD2;
            const __half2* r1 = g_p1h + (size_t)s1 * P1_LD2;
            const __half2* r2 = g_p1h + (size_t)s2 * P1_LD2;
            const __half2* r3 = g_p1h + (size_t)s3 * P1_LD2;
            // 4 independent low-loads (all lanes) — issued back-to-back
            __half2 x0 = r0[lane], x1 = r1[lane], x2 = r2[lane], x3 = r3[lane];
            float2 f0 = __half22float2(x0), f1 = __half22float2(x1);
            float2 f2 = __half22float2(x2), f3 = __half22float2(x3);
            a0x += (f0.x + f1.x) + (f2.x + f3.x);
            a0y += (f0.y + f1.y) + (f2.y + f3.y);
            if (hib) {             // 4 independent high-loads (lanes < 18)
                __half2 y0 = r0[32 + lane], y1 = r1[32 + lane];
                __half2 y2 = r2[32 + lane], y3 = r3[32 + lane];
                float2 g0 = __half22float2(y0), g1 = __half22float2(y1);
                float2 g2 = __half22float2(y2), g3 = __half22float2(y3);
                a1x += (g0.x + g1.x) + (g2.x + g3.x);
                a1y += (g0.y + g1.y) + (g2.y + g3.y);
            }
        }
    }
    int rem = deg - nfull;
    if (rem) {
        int s = (lane < rem) ? g_csr[start + nfull + lane] : 0;
        for (int j = 0; j < rem; j++) {
            int sj = __shfl_sync(0xffffffffu, s, j);
            const __half2* row = g_p1h + (size_t)sj * P1_LD2;
            float2 v0 = __half22float2(row[lane]);
            a0x += v0.x; a0y += v0.y;
            if (hib) {
                float2 v1 = __half22float2(row[32 + lane]);
                a1x += v1.x; a1y += v1.y;
            }
        }
    }
    if (deg > 0) {
        float inv = 1.0f / (float)deg;
        a0x *= inv; a0y *= inv; a1x *= inv; a1y *= inv;
    } else {
        const __half2* row = g_p1h + (size_t)gw * P1_LD2;
        float2 v0 = __half22float2(row[lane]);
        a0x = v0.x; a0y = v0.y;
        if (hib) {
            float2 v1 = __half22float2(row[32 + lane]);
            a1x = v1.x; a1y = v1.y;
        }
    }
    const float2* b1v = (const float2*)b1;
    float2 bb = b1v[lane];
    ((float2*)h1s[w])[lane] = make_float2(fmaxf(a0x + bb.x, 0.f),
                                          fmaxf(a0y + bb.y, 0.f));
    if (hib) {
        float2 bc = b1v[32 + lane];
        ((float2*)h1s[w])[32 + lane] = make_float2(fmaxf(a1x + bc.x, 0.f),
                                                   fmaxf(a1y + bc.y, 0.f));
    }
    __syncthreads();   // w2s staging + h1s visible

    // GEMM2: p2[gw][c] = sum_k h1s[w][k] * W2[k][c], c = lane < 20
    float acc = 0.f;
    if (lane < D2) {
        #pragma unroll
        for (int k = 0; k < D1; k++)
            acc += h1s[w][k] * w2s[k * D2 + lane];
    }
    float hi = __shfl_down_sync(0xffffffffu, acc, 1);
    if (lane < D2 && (lane & 1) == 0)
        g_p2h[(size_t)gw * P2_LD2 + (lane >> 1)] = __floats2half2_rn(acc, hi);
}

// ---------------- Aggregation layer 2 (4 edges/iter) + fused pool -----------
// half = lane>>4 selects edge parity; idx = lane&15 (<10 active half2 chunks).
__global__ void k_agg2pool(const float* __restrict__ b2, const int* __restrict__ gid) {
    int gw   = (blockIdx.x * blockDim.x + threadIdx.x) >> 5;
    int lane = threadIdx.x & 31;
    int start = g_rowptr[gw], end = g_rowptr[gw + 1];
    int deg = end - start;
    int half = lane >> 4;
    int idx  = lane & 15;
    bool iact = idx < 10;
    float ax = 0.f, ay = 0.f;
    for (int eb = start; eb < end; eb += 32) {
        int n = min(32, end - eb);
        int s = (lane < n) ? g_csr[eb + lane] : 0;
        for (int j = 0; j < n; j += 4) {
            int ja = j + half;          // edges j, j+1
            int jb = j + 2 + half;      // edges j+2, j+3
            int sa = __shfl_sync(0xffffffffu, s, ja & 31);
            int sb = __shfl_sync(0xffffffffu, s, jb & 31);
            bool qa = iact & (ja < n);
            bool qb = iact & (jb < n);
            __half2 pa, pb;             // two independent loads -> MLP 2
            if (qa) pa = g_p2h[(size_t)sa * P2_LD2 + idx];
            if (qb) pb = g_p2h[(size_t)sb * P2_LD2 + idx];
            if (qa) { float2 f = __half22float2(pa); ax += f.x; ay += f.y; }
            if (qb) { float2 f = __half22float2(pb); ax += f.x; ay += f.y; }
        }
    }
    // combine even/odd partial sums
    ax += __shfl_xor_sync(0xffffffffu, ax, 16);
    ay += __shfl_xor_sync(0xffffffffu, ay, 16);

    int g = gid[gw];
    if (lane < 10) {
        float vx, vy;
        if (deg > 0) {
            float inv = 1.0f / (float)deg;
            vx = ax * inv; vy = ay * inv;
        } else {
            float2 v = __half22float2(g_p2h[(size_t)gw * P2_LD2 + lane]);
            vx = v.x; vy = v.y;
        }
        const float2* b2v = (const float2*)b2;
        float2 bb = b2v[lane];
        atomicAdd(&g_hg[g * D2 + 2 * lane],     fmaxf(vx + bb.x, 0.f));
        atomicAdd(&g_hg[g * D2 + 2 * lane + 1], fmaxf(vy + bb.y, 0.f));
    }
    if (lane == 0) atomicAdd(&g_gcnt[g], 1);
}

// ---------------- gate + MLP decoder (256 graphs, 1 block) ------------------
// Re-zeroes g_hg / g_gcnt after reading (restores the call-entry invariant).
__global__ void k_final(const float* __restrict__ self_feat,
                        const float* __restrict__ Wp,  const float* __restrict__ bp,
                        const float* __restrict__ Wf1, const float* __restrict__ bf1,
                        const float* __restrict__ Wf2, const float* __restrict__ bf2,
                        float* __restrict__ out) {
    __shared__ float swp[DIM_SELF * D2];
    __shared__ float sbp[D2], swf1[D2 * 10], sbf1[10], swf2[10], sbf2;
    int t = threadIdx.x;
    for (int i = t; i < DIM_SELF * D2; i += 256) swp[i] = Wp[i];
    for (int i = t; i < D2 * 10; i += 256) swf1[i] = Wf1[i];
    if (t < D2) sbp[t] = bp[t];
    if (t < 10) { sbf1[t] = bf1[t]; swf2[t] = Wf2[t]; }
    if (t == 0) sbf2 = bf2[0];
    __syncthreads();

    int g = t;
    float hg[D2], z[D2];
    int c = g_gcnt[g];
    float invc = 1.0f / (float)max(c, 1);
    #pragma unroll
    for (int j = 0; j < D2; j++) { hg[j] = g_hg[g * D2 + j] * invc; z[j] = sbp[j]; }
    #pragma unroll
    for (int j = 0; j < D2; j++) g_hg[g * D2 + j] = 0.f;   // restore invariant
    g_gcnt[g] = 0;

    for (int i = 0; i < DIM_SELF; i++) {
        float sv = self_feat[g * DIM_SELF + i];
        #pragma unroll
        for (int j = 0; j < D2; j++) z[j] += sv * swp[i * D2 + j];
    }
    float m[10];
    #pragma unroll
    for (int o = 0; o < 10; o++) m[o] = sbf1[o];
    #pragma unroll
    for (int j = 0; j < D2; j++) {
        float p    = hg[j] * z[j];
        float gate = 1.0f / (1.0f + expf(-p));
        float f    = gate * hg[j] + (1.0f - gate) * z[j];
        #pragma unroll
        for (int o = 0; o < 10; o++) m[o] += f * swf1[j * 10 + o];
    }
    float o0 = sbf2;
    #pragma unroll
    for (int o = 0; o < 10; o++) o0 += fmaxf(m[o], 0.f) * swf2[o];
    out[g] = o0;
}

// ---------------- launch -----------------------------------------------------
extern "C" void kernel_launch(void* const* d_in, const int* in_sizes, int n_in,
                              void* d_out, int out_size) {
    const float* feat      = (const float*)d_in[0];
    const int*   src       = (const int*)  d_in[1];
    const int*   dst       = (const int*)  d_in[2];
    const int*   gid       = (const int*)  d_in[3];
    const float* self_feat = (const float*)d_in[4];
    const float* W1  = (const float*)d_in[5];
    const float* b1  = (const float*)d_in[6];
    const float* W2  = (const float*)d_in[7];
    const float* b2  = (const float*)d_in[8];
    const float* Wp  = (const float*)d_in[9];
    const float* bp  = (const float*)d_in[10];
    const float* Wf1 = (const float*)d_in[11];
    const float* bf1 = (const float*)d_in[12];
    const float* Wf2 = (const float*)d_in[13];
    const float* bf2 = (const float*)d_in[14];
    float* out = (float*)d_out;

    k_count   <<<(N_EDGES / 4 + 255) / 256, 256>>>(dst, W1);
    k_scan    <<<1, 1024>>>();
    k_fill    <<<(N_EDGES / 4 + 255) / 256, 256>>>(src, dst);
    k_gemm1   <<<(N_NODES + 63) / 64, 256>>>(feat);
    k_agg1g2  <<<N_NODES / 8, 256>>>(b1, W2);
    k_agg2pool<<<N_NODES / 8, 256>>>(b2, gid);
    k_final   <<<1, 256>>>(self_feat, Wp, bp, Wf1, bf1, Wf2, bf2, out);
}

// round 15
// speedup vs baseline: 1.1208x; 1.1206x over previous
#include <cuda_runtime.h>
#include <cuda_fp16.h>
#include <mma.h>
#include <math.h>

using namespace nvcuda;

#define N_NODES   50000
#define N_EDGES   1600000
#define N_GRAPHS  256
#define DIM_IN    128
#define D1        100
#define D2        20
#define DIM_SELF  64

#define P1_LD2    64          // p1 row stride in half2 (128 halfs = 256B aligned)
#define P1_ROWS   50048       // padded to 64-row multiple: unguarded wmma stores
#define P2_LD2    16          // p2 row stride in half2 (32 halfs = 64B aligned)
#define W1_LD     112         // padded W1 cols (halfs)
#define AH_LD     136         // Ah smem row stride in halfs (272B -> conflict-free LDSM)

// ---------------- scratch (device globals; no allocation allowed) -----------
// Invariant: g_cnt / g_hg / g_gcnt are zero on entry to every call (zero-init
// at load; re-zeroed by the kernels that consume them).
__device__ __align__(16) int     g_cnt[N_NODES];
__device__ __align__(16) int     g_rowptr[N_NODES + 1];
__device__ __align__(16) int     g_posn[N_EDGES];
__device__ __align__(16) int     g_csr[N_EDGES];
__device__ __align__(16) __half  g_w1h[128 * W1_LD];        // W1 fp16 (refreshed per call)
__device__ __align__(16) __half2 g_p1h[P1_ROWS * P1_LD2];   // feat @ W1 (fp16)
__device__ __align__(16) __half2 g_p2h[N_NODES * P2_LD2];   // h1 @ W2 (fp16)
__device__ __align__(16) float   g_hg[N_GRAPHS * D2];
__device__ __align__(16) int     g_gcnt[N_GRAPHS];

// ---------------- CSR count (single atomic pass) + W1 fp16 convert ----------
__global__ void k_count(const int* __restrict__ dst, const float* __restrict__ W1) {
    int e4 = blockIdx.x * blockDim.x + threadIdx.x;
    if (e4 < 128 * W1_LD) {                  // piggyback: W1 -> fp16
        int k = e4 / W1_LD, c = e4 - k * W1_LD;
        g_w1h[e4] = (c < D1) ? __float2half(W1[k * D1 + c]) : __float2half(0.f);
    }
    if (e4 >= N_EDGES / 4) return;
    int4 d = ((const int4*)dst)[e4];
    int4 p;
    p.x = atomicAdd(&g_cnt[d.x], 1);
    p.y = atomicAdd(&g_cnt[d.y], 1);
    p.z = atomicAdd(&g_cnt[d.z], 1);
    p.w = atomicAdd(&g_cnt[d.w], 1);
    ((int4*)g_posn)[e4] = p;
}

// single-block exclusive scan of g_cnt -> g_rowptr (int4, CH=52);
// re-zeroes g_cnt after reading (restores the call-entry invariant).
__global__ void k_scan() {
    __shared__ int ss[1024];
    const int CH = 52;                       // 13 int4 per thread
    int t = threadIdx.x;
    int base = t * CH;
    int s = 0;
    if (base + CH <= N_NODES) {
        const int4* p = (const int4*)(g_cnt + base);
        #pragma unroll
        for (int i = 0; i < 13; i++) { int4 v = p[i]; s += v.x + v.y + v.z + v.w; }
    } else {
        for (int i = base; i < N_NODES; i++) s += g_cnt[i];
    }
    ss[t] = s;
    __syncthreads();
    for (int off = 1; off < 1024; off <<= 1) {
        int v = (t >= off) ? ss[t - off] : 0;
        __syncthreads();
        ss[t] += v;
        __syncthreads();
    }
    int run = (t == 0) ? 0 : ss[t - 1];
    if (base + CH <= N_NODES) {
        const int4* p = (const int4*)(g_cnt + base);
        int4* q = (int4*)(g_rowptr + base);
        int4* z = (int4*)(g_cnt + base);
        #pragma unroll
        for (int i = 0; i < 13; i++) {
            int4 v = p[i];
            int4 o;
            o.x = run; run += v.x;
            o.y = run; run += v.y;
            o.z = run; run += v.z;
            o.w = run; run += v.w;
            q[i] = o;
            z[i] = make_int4(0, 0, 0, 0);
        }
    } else {
        for (int i = base; i < N_NODES; i++) {
            g_rowptr[i] = run; run += g_cnt[i]; g_cnt[i] = 0;
        }
    }
    if (t == 0) g_rowptr[N_NODES] = N_EDGES;
}

// atomic-free fill: slot known from recorded position
__global__ void k_fill(const int* __restrict__ src, const int* __restrict__ dst) {
    int e4 = blockIdx.x * blockDim.x + threadIdx.x;
    if (e4 >= N_EDGES / 4) return;
    int4 d = ((const int4*)dst)[e4];
    int4 p = ((const int4*)g_posn)[e4];
    int4 s = ((const int4*)src)[e4];
    g_csr[g_rowptr[d.x] + p.x] = s.x;
    g_csr[g_rowptr[d.y] + p.y] = s.y;
    g_csr[g_rowptr[d.z] + p.z] = s.z;
    g_csr[g_rowptr[d.w] + p.w] = s.w;
}

// ---------------- GEMM1: p1 = feat @ W1 via HMMA ----------------------------
// 64 rows/block, 8 warps. A staged in smem with 272B rows (conflict-free LDSM);
// B fragments read directly from global g_w1h (L1-resident, 28KB);
// fp16 accumulators stored straight to padded g_p1h — no smem round-trip.
__global__ void k_gemm1(const float* __restrict__ feat) {
    __shared__ __align__(16) __half Ah[64 * AH_LD];   // 17408 B
    int t  = threadIdx.x;
    int r0 = blockIdx.x * 64;

    for (int i = t; i < 64 * 32; i += 256) {
        int r = i >> 5, q = i & 31;
        float4 f = (r0 + r < N_NODES)
                 ? ((const float4*)feat)[(size_t)(r0 + r) * 32 + q]
                 : make_float4(0.f, 0.f, 0.f, 0.f);
        __half2* a2 = (__half2*)(Ah + r * AH_LD + q * 4);
        a2[0] = __floats2half2_rn(f.x, f.y);
        a2[1] = __floats2half2_rn(f.z, f.w);
    }
    __syncthreads();

    int w     = t >> 5;
    int strip = w >> 1;                  // 16-row strip 0..3
    int ct0   = (w & 1) ? 4 : 0;         // col tiles {0..3} / {4..6}
    int nct   = (w & 1) ? 3 : 4;

    wmma::fragment<wmma::accumulator, 16, 16, 16, __half> acc[4];
    for (int c = 0; c < 4; c++) wmma::fill_fragment(acc[c], __float2half(0.f));

    for (int k8 = 0; k8 < 8; k8++) {
        wmma::fragment<wmma::matrix_a, 16, 16, 16, __half, wmma::row_major> af;
        wmma::load_matrix_sync(af, Ah + strip * 16 * AH_LD + k8 * 16, AH_LD);
        for (int c = 0; c < nct; c++) {
            wmma::fragment<wmma::matrix_b, 16, 16, 16, __half, wmma::row_major> bf;
            wmma::load_matrix_sync(bf, g_w1h + (k8 * 16) * W1_LD + (ct0 + c) * 16, W1_LD);
            wmma::mma_sync(acc[c], af, bf, acc[c]);
        }
    }

    __half* out = (__half*)g_p1h;        // row stride 128 halfs; rows padded
    for (int c = 0; c < nct; c++)
        wmma::store_matrix_sync(out + (size_t)(r0 + strip * 16) * 128 + (ct0 + c) * 16,
                                acc[c], 128, wmma::mem_row_major);
}

// ---------------- Fused: aggregation-1 + relu + GEMM2 (round-10 form) -------
// 8 warps, 1 node per warp; h1 row lands in smem; lanes 0..19 then do the
// 100x20 projection against smem W2 and write p2 (fp16).
__global__ void k_agg1g2(const float* __restrict__ b1, const float* __restrict__ W2) {
    __shared__ float h1s[8][104];
    __shared__ float w2s[D1 * D2];     // 8000 B
    int t = threadIdx.x, w = t >> 5, lane = t & 31;

    for (int i = t; i < D1 * D2; i += 256) w2s[i] = W2[i];

    int gw = blockIdx.x * 8 + w;       // grid*8 == N_NODES exactly
    int start = g_rowptr[gw], end = g_rowptr[gw + 1];
    int deg = end - start;
    float a0x = 0.f, a0y = 0.f, a1x = 0.f, a1y = 0.f;

    int nfull = deg & ~31;
    for (int eb = start; eb < start + nfull; eb += 32) {
        int s = g_csr[eb + lane];
        #pragma unroll 8
        for (int j = 0; j < 32; j++) {
            int sj = __shfl_sync(0xffffffffu, s, j);
            const __half2* row = g_p1h + (size_t)sj * P1_LD2;
            float2 v0 = __half22float2(row[lane]);
            a0x += v0.x; a0y += v0.y;
            if (lane < 18) {
                float2 v1 = __half22float2(row[32 + lane]);
                a1x += v1.x; a1y += v1.y;
            }
        }
    }
    int rem = deg - nfull;
    if (rem) {
        int s = (lane < rem) ? g_csr[start + nfull + lane] : 0;
        for (int j = 0; j < rem; j++) {
            int sj = __shfl_sync(0xffffffffu, s, j);
            const __half2* row = g_p1h + (size_t)sj * P1_LD2;
            float2 v0 = __half22float2(row[lane]);
            a0x += v0.x; a0y += v0.y;
            if (lane < 18) {
                float2 v1 = __half22float2(row[32 + lane]);
                a1x += v1.x; a1y += v1.y;
            }
        }
    }
    if (deg > 0) {
        float inv = 1.0f / (float)deg;
        a0x *= inv; a0y *= inv; a1x *= inv; a1y *= inv;
    } else {
        const __half2* row = g_p1h + (size_t)gw * P1_LD2;
        float2 v0 = __half22float2(row[lane]);
        a0x = v0.x; a0y = v0.y;
        if (lane < 18) {
            float2 v1 = __half22float2(row[32 + lane]);
            a1x = v1.x; a1y = v1.y;
        }
    }
    const float2* b1v = (const float2*)b1;
    float2 bb = b1v[lane];
    ((float2*)h1s[w])[lane] = make_float2(fmaxf(a0x + bb.x, 0.f),
                                          fmaxf(a0y + bb.y, 0.f));
    if (lane < 18) {
        float2 bc = b1v[32 + lane];
        ((float2*)h1s[w])[32 + lane] = make_float2(fmaxf(a1x + bc.x, 0.f),
                                                   fmaxf(a1y + bc.y, 0.f));
    }
    __syncthreads();

    // GEMM2: p2[gw][c] = sum_k h1s[w][k] * W2[k][c], c = lane < 20
    float acc = 0.f;
    if (lane < D2) {
        #pragma unroll
        for (int k = 0; k < D1; k++)
            acc += h1s[w][k] * w2s[k * D2 + lane];
    }
    float hi = __shfl_down_sync(0xffffffffu, acc, 1);
    if (lane < D2 && (lane & 1) == 0)
        g_p2h[(size_t)gw * P2_LD2 + (lane >> 1)] = __floats2half2_rn(acc, hi);
}

// ---------------- Aggregation layer 2 + fused pool (round-10 form) ----------
__global__ void k_agg2pool(const float* __restrict__ b2, const int* __restrict__ gid) {
    int gw   = (blockIdx.x * blockDim.x + threadIdx.x) >> 5;
    int lane = threadIdx.x & 31;
    int start = g_rowptr[gw], end = g_rowptr[gw + 1];
    int deg = end - start;
    int half = lane >> 4;       // 0: even edges, 1: odd edges
    int idx  = lane & 15;       // half2 index within row (<10 active)
    float ax = 0.f, ay = 0.f;
    for (int eb = start; eb < end; eb += 32) {
        int n = min(32, end - eb);
        int s = (lane < n) ? g_csr[eb + lane] : 0;
        for (int j = 0; j < n; j += 2) {
            int je = j + half;
            int sj = __shfl_sync(0xffffffffu, s, je);
            if (idx < 10 && je < n) {
                float2 v = __half22float2(g_p2h[(size_t)sj * P2_LD2 + idx]);
                ax += v.x; ay += v.y;
            }
        }
    }
    ax += __shfl_xor_sync(0xffffffffu, ax, 16);
    ay += __shfl_xor_sync(0xffffffffu, ay, 16);

    int g = gid[gw];
    if (lane < 10) {
        float vx, vy;
        if (deg > 0) {
            float inv = 1.0f / (float)deg;
            vx = ax * inv; vy = ay * inv;
        } else {
            float2 v = __half22float2(g_p2h[(size_t)gw * P2_LD2 + lane]);
            vx = v.x; vy = v.y;
        }
        const float2* b2v = (const float2*)b2;
        float2 bb = b2v[lane];
        atomicAdd(&g_hg[g * D2 + 2 * lane],     fmaxf(vx + bb.x, 0.f));
        atomicAdd(&g_hg[g * D2 + 2 * lane + 1], fmaxf(vy + bb.y, 0.f));
    }
    if (lane == 0) atomicAdd(&g_gcnt[g], 1);
}

// ---------------- gate + MLP decoder (256 graphs, 1 block) ------------------
// Re-zeroes g_hg / g_gcnt after reading (restores the call-entry invariant).
__global__ void k_final(const float* __restrict__ self_feat,
                        const float* __restrict__ Wp,  const float* __restrict__ bp,
                        const float* __restrict__ Wf1, const float* __restrict__ bf1,
                        const float* __restrict__ Wf2, const float* __restrict__ bf2,
                        float* __restrict__ out) {
    __shared__ float swp[DIM_SELF * D2];
    __shared__ float sbp[D2], swf1[D2 * 10], sbf1[10], swf2[10], sbf2;
    int t = threadIdx.x;
    for (int i = t; i < DIM_SELF * D2; i += 256) swp[i] = Wp[i];
    for (int i = t; i < D2 * 10; i += 256) swf1[i] = Wf1[i];
    if (t < D2) sbp[t] = bp[t];
    if (t < 10) { sbf1[t] = bf1[t]; swf2[t] = Wf2[t]; }
    if (t == 0) sbf2 = bf2[0];
    __syncthreads();

    int g = t;
    float hg[D2], z[D2];
    int c = g_gcnt[g];
    float invc = 1.0f / (float)max(c, 1);
    #pragma unroll
    for (int j = 0; j < D2; j++) { hg[j] = g_hg[g * D2 + j] * invc; z[j] = sbp[j]; }
    #pragma unroll
    for (int j = 0; j < D2; j++) g_hg[g * D2 + j] = 0.f;   // restore invariant
    g_gcnt[g] = 0;

    for (int i = 0; i < DIM_SELF; i++) {
        float sv = self_feat[g * DIM_SELF + i];
        #pragma unroll
        for (int j = 0; j < D2; j++) z[j] += sv * swp[i * D2 + j];
    }
    float m[10];
    #pragma unroll
    for (int o = 0; o < 10; o++) m[o] = sbf1[o];
    #pragma unroll
    for (int j = 0; j < D2; j++) {
        float p    = hg[j] * z[j];
        float gate = 1.0f / (1.0f + expf(-p));
        float f    = gate * hg[j] + (1.0f - gate) * z[j];
        #pragma unroll
        for (int o = 0; o < 10; o++) m[o] += f * swf1[j * 10 + o];
    }
    float o0 = sbf2;
    #pragma unroll
    for (int o = 0; o < 10; o++) o0 += fmaxf(m[o], 0.f) * swf2[o];
    out[g] = o0;
}

// ---------------- launch -----------------------------------------------------
extern "C" void kernel_launch(void* const* d_in, const int* in_sizes, int n_in,
                              void* d_out, int out_size) {
    const float* feat      = (const float*)d_in[0];
    const int*   src       = (const int*)  d_in[1];
    const int*   dst       = (const int*)  d_in[2];
    const int*   gid       = (const int*)  d_in[3];
    const float* self_feat = (const float*)d_in[4];
    const float* W1  = (const float*)d_in[5];
    const float* b1  = (const float*)d_in[6];
    const float* W2  = (const float*)d_in[7];
    const float* b2  = (const float*)d_in[8];
    const float* Wp  = (const float*)d_in[9];
    const float* bp  = (const float*)d_in[10];
    const float* Wf1 = (const float*)d_in[11];
    const float* bf1 = (const float*)d_in[12];
    const float* Wf2 = (const float*)d_in[13];
    const float* bf2 = (const float*)d_in[14];
    float* out = (float*)d_out;

    k_count   <<<(N_EDGES / 4 + 255) / 256, 256>>>(dst, W1);
    k_scan    <<<1, 1024>>>();
    k_fill    <<<(N_EDGES / 4 + 255) / 256, 256>>>(src, dst);
    k_gemm1   <<<(N_NODES + 63) / 64, 256>>>(feat);
    k_agg1g2  <<<N_NODES / 8, 256>>>(b1, W2);
    k_agg2pool<<<N_NODES / 8, 256>>>(b2, gid);
    k_final   <<<1, 256>>>(self_feat, Wp, bp, Wf1, bf1, Wf2, bf2, out);
}